// round 16
// baseline (speedup 1.0000x reference)
#include <cuda_runtime.h>
#include <cuda_bf16.h>
#include <math.h>

#define Bq 64
#define Nn 1024
#define Ee 16384
#define Ff 128
#define Hh 64
#define Tt 10
#define BN (Bq*Nn)   // 65536

// agg1 dynamic smem: 128KB features + st(2560) + bias(256)
#define AGG_SMEM (131072 + 2560 + 256)

// ---------------- scratch (static device globals; no allocs allowed) --------
__device__ __nv_bfloat16 g_A[BN*Hh]; // layer1: bf16 invs[n]*(x@W1)[n]
__device__ int      g_csr[Bq*Ee];    // CSR-by-dst: LOCAL src ids (0..1023)
__device__ int      g_off[BN];       // absolute start offset into g_csr
__device__ int      g_indeg[BN];
__device__ unsigned g_mask[BN];      // 10-bit token->node mask
__device__ float    g_invs[BN];      // 1/sqrt(deg_node)
__device__ float    g_w[BN];         // invs[n]*(w[n]+invs[n]) pooling weight
__device__ float    g_tm[Bq*Tt];     // tmask[g][t] = sum_n mask[n,t]*invs[n]
__device__ float    g_st1[Tt*Hh];    // invsT[t] * (tokens@W1)[t,:]
__device__ float    g_st2p[Tt*Hh];   // invsT[t] * h1a_tok[t,:]  (pre-W2 cross)
__device__ float    g_toksum[Hh];    // sum_t out_tok2[t,:]
__device__ float    g_P[Bq*Hh];      // pooled pre-W2 node vectors (atomic accum)

// ---- helpers ----------------------------------------------------------------
__device__ __forceinline__ void acc_bf16x8(float* a, uint4 v) {
    a[0] += __uint_as_float(v.x << 16);
    a[1] += __uint_as_float(v.x & 0xffff0000u);
    a[2] += __uint_as_float(v.y << 16);
    a[3] += __uint_as_float(v.y & 0xffff0000u);
    a[4] += __uint_as_float(v.z << 16);
    a[5] += __uint_as_float(v.z & 0xffff0000u);
    a[6] += __uint_as_float(v.w << 16);
    a[7] += __uint_as_float(v.w & 0xffff0000u);
}
__device__ __forceinline__ unsigned pack_bf16x2(float a, float b) {
    __nv_bfloat162 p = __float22bfloat162_rn(make_float2(a, b));
    return *reinterpret_cast<unsigned*>(&p);
}

// ---------------- CSR build (blocks 0-63) + token stream (block 64) ---------
__global__ void csr_token_kernel(const int* __restrict__ esrc, const int* __restrict__ edst,
                                 const float* __restrict__ tok,
                                 const float* __restrict__ W1, const float* __restrict__ b1,
                                 const float* __restrict__ W2, const float* __restrict__ b2)
{
    __shared__ union {
        struct { int cnt[Nn]; int wsum[32]; } c;
        struct {
            float tk[Tt][129];
            float nrm[Tt][Tt];
            float invsT[Tt], invdT[Tt];
            float h1l[Tt][Hh], h1a[Tt][Hh], h2l[Tt][Hh], ot2[Tt][Hh];
        } t;
    } u;
    int tid = threadIdx.x;

    if (blockIdx.x < Bq) {
        int b = blockIdx.x;
        int lane = tid & 31, wid = tid >> 5;
        u.c.cnt[tid] = 0;
        __syncthreads();
        const int* dp = edst + b*Ee;
        const int* sp = esrc + b*Ee;
        for (int e = tid; e < Ee; e += Nn) atomicAdd(&u.c.cnt[dp[e]], 1);
        __syncthreads();
        int c = u.c.cnt[tid];
        g_indeg[b*Nn + tid] = c;
        int v = c;
        for (int d = 1; d < 32; d <<= 1) {
            int uu = __shfl_up_sync(0xffffffffu, v, d);
            if (lane >= d) v += uu;
        }
        if (lane == 31) u.c.wsum[wid] = v;
        __syncthreads();
        if (tid < 32) {
            int s = u.c.wsum[tid];
            for (int d = 1; d < 32; d <<= 1) {
                int uu = __shfl_up_sync(0xffffffffu, s, d);
                if (tid >= d) s += uu;
            }
            u.c.wsum[tid] = s;
        }
        __syncthreads();
        int base = wid ? u.c.wsum[wid-1] : 0;
        int pos0 = b*Ee + base + (v - c);
        g_off[b*Nn + tid] = pos0;
        __syncthreads();
        u.c.cnt[tid] = pos0;
        __syncthreads();
        for (int e = tid; e < Ee; e += Nn) {
            int d = dp[e];
            int p = atomicAdd(&u.c.cnt[d], 1);
            g_csr[p] = sp[e];                 // LOCAL src id
        }
    } else {
        const int NT = 1024;
        for (int i = tid; i < Tt*Ff; i += NT) u.t.tk[i/Ff][i%Ff] = tok[i];
        __syncthreads();
        if (tid < Tt*Tt) {
            int i = tid/Tt, j = tid%Tt;
            float d = 0.f;
            for (int f = 0; f < Ff; f++) d += u.t.tk[i][f]*u.t.tk[j][f];
            float s = 1.f/(1.f+expf(-d));
            u.t.nrm[i][j] = (s >= 0.3f) ? 1.f : 0.f;
        }
        __syncthreads();
        if (tid < Tt) {
            float deg = 1.f;
            for (int i = 0; i < Tt; i++) deg += u.t.nrm[i][tid];
            u.t.invsT[tid] = rsqrtf(deg);
            u.t.invdT[tid] = 1.f/deg;
        }
        __syncthreads();
        if (tid < Tt*Tt) {
            int i = tid/Tt, j = tid%Tt;
            u.t.nrm[i][j] *= u.t.invsT[i]*u.t.invsT[j];
        }
        for (int idx = tid; idx < Tt*Hh; idx += NT) {
            int t = idx/Hh, h = idx%Hh;
            float a = 0.f;
            for (int f = 0; f < Ff; f++) a += u.t.tk[t][f]*W1[f*Hh+h];
            u.t.h1l[t][h] = a;
        }
        __syncthreads();
        for (int idx = tid; idx < Tt*Hh; idx += NT) {
            int t = idx/Hh, h = idx%Hh;
            float a = u.t.h1l[t][h]*u.t.invdT[t] + b1[h];
            for (int j = 0; j < Tt; j++) a += u.t.nrm[t][j]*u.t.h1l[j][h];
            float act = (a >= 0.f) ? a : 0.01f*a;
            u.t.h1a[t][h] = act;
            g_st1[idx]  = u.t.invsT[t]*u.t.h1l[t][h];
            g_st2p[idx] = u.t.invsT[t]*act;
        }
        __syncthreads();
        for (int idx = tid; idx < Tt*Hh; idx += NT) {
            int t = idx/Hh, h = idx%Hh;
            float a = 0.f;
            for (int k = 0; k < Hh; k++) a += u.t.h1a[t][k]*W2[k*Hh+h];
            u.t.h2l[t][h] = a;
        }
        __syncthreads();
        for (int idx = tid; idx < Tt*Hh; idx += NT) {
            int t = idx/Hh, h = idx%Hh;
            float a = u.t.h2l[t][h]*u.t.invdT[t] + b2[h];
            for (int j = 0; j < Tt; j++) a += u.t.nrm[t][j]*u.t.h2l[j][h];
            u.t.ot2[t][h] = a;
        }
        __syncthreads();
        if (tid < Hh) {
            float s = 0.f;
            for (int t = 0; t < Tt; t++) s += u.t.ot2[t][tid];
            g_toksum[tid] = s;
        }
        for (int i = tid; i < Bq*Hh; i += NT) g_P[i] = 0.f;
    }
}

// ------- fused x-pass: tf32 MMA for x@W1, fp32 token dots -> mask, deg ------
__global__ void xpass_kernel(const float* __restrict__ x, const float* __restrict__ W1,
                             const float* __restrict__ tok)
{
    __shared__ float xs2[64][68];
    __shared__ float ws[64][68];
    __shared__ float ts[Tt][64];
    __shared__ unsigned maskbuf[64];
    __shared__ float invsS[64];
    int tid = threadIdx.x;
    int bn0 = blockIdx.x * 64;
    int w = tid >> 5, t = tid & 31;
    int m0 = (w & 3) * 16;
    int h0 = (w >> 2) * 32;
    int ty = t >> 2, tk = t & 3;

    float acc[4][4];
    #pragma unroll
    for (int i = 0; i < 4; i++)
        #pragma unroll
        for (int j = 0; j < 4; j++) acc[i][j] = 0.f;
    float dacc[3] = {0.f, 0.f, 0.f};
    if (tid < 64) maskbuf[tid] = 0u;

    for (int c = 0; c < 2; c++) {
        __syncthreads();
        for (int idx = tid; idx < 4096; idx += 256) {
            int f = idx & 63, n = idx >> 6;
            xs2[n][f] = x[(bn0+n)*Ff + c*64 + f];
        }
        for (int idx = tid; idx < 4096; idx += 256) {
            int h = idx & 63, f = idx >> 6;
            ws[f][h] = W1[(c*64+f)*Hh + h];
        }
        for (int idx = tid; idx < Tt*64; idx += 256) {
            int f = idx & 63, tt = idx >> 6;
            ts[tt][f] = tok[tt*Ff + c*64 + f];
        }
        __syncthreads();
        #pragma unroll
        for (int r = 0; r < 3; r++) {
            int idx = tid + r*256;
            if (idx < 640) {
                int n = idx & 63, tt = idx >> 6;
                float a = dacc[r];
                #pragma unroll 8
                for (int f = 0; f < 64; f++) a += xs2[n][f]*ts[tt][f];
                dacc[r] = a;
            }
        }
        #pragma unroll
        for (int k8 = 0; k8 < 8; k8++) {
            int k0 = k8*8;
            unsigned a0 = __float_as_uint(xs2[m0+ty  ][k0+tk  ]);
            unsigned a1 = __float_as_uint(xs2[m0+ty+8][k0+tk  ]);
            unsigned a2 = __float_as_uint(xs2[m0+ty  ][k0+tk+4]);
            unsigned a3 = __float_as_uint(xs2[m0+ty+8][k0+tk+4]);
            #pragma unroll
            for (int ns = 0; ns < 4; ns++) {
                unsigned b0 = __float_as_uint(ws[k0+tk  ][h0+ns*8+ty]);
                unsigned b1 = __float_as_uint(ws[k0+tk+4][h0+ns*8+ty]);
                asm volatile(
                    "mma.sync.aligned.m16n8k8.row.col.f32.tf32.tf32.f32 "
                    "{%0,%1,%2,%3},{%4,%5,%6,%7},{%8,%9},{%0,%1,%2,%3};"
                    : "+f"(acc[ns][0]), "+f"(acc[ns][1]),
                      "+f"(acc[ns][2]), "+f"(acc[ns][3])
                    : "r"(a0), "r"(a1), "r"(a2), "r"(a3), "r"(b0), "r"(b1));
            }
        }
    }
    #pragma unroll
    for (int r = 0; r < 3; r++) {
        int idx = tid + r*256;
        if (idx < 640) {
            int n = idx & 63, tt = idx >> 6;
            float s = 1.f/(1.f+expf(-dacc[r]));
            if (s >= 0.1f) atomicOr(&maskbuf[n], 1u << tt);
        }
    }
    __syncthreads();
    if (tid < 64) {
        int bn = bn0 + tid;
        unsigned m = maskbuf[tid];
        float deg = 1.0f + (float)g_indeg[bn] + (float)__popc(m);
        float is = rsqrtf(deg);
        g_mask[bn] = m;
        g_invs[bn] = is;
        invsS[tid] = is;
    }
    __syncthreads();
    {
        unsigned* A32 = (unsigned*)g_A;
        int r0 = m0 + ty, r1 = r0 + 8;
        float s0 = invsS[r0], s1 = invsS[r1];
        int cb = (h0 >> 1) + tk;
        #pragma unroll
        for (int ns = 0; ns < 4; ns++) {
            A32[(bn0+r0)*32 + cb + ns*4] = pack_bf16x2(acc[ns][0]*s0, acc[ns][1]*s0);
            A32[(bn0+r1)*32 + cb + ns*4] = pack_bf16x2(acc[ns][2]*s1, acc[ns][3]*s1);
        }
    }
}

// ------- per-graph source weights + token-mask sums -------------------------
__global__ void wtok_kernel(const int* __restrict__ esrc, const int* __restrict__ edst)
{
    __shared__ float invs_s[Nn];
    __shared__ float w_s[Nn];
    __shared__ float tm[Tt];
    int g = blockIdx.x, tid = threadIdx.x;
    int lane = tid & 31;
    invs_s[tid] = g_invs[g*Nn + tid];
    w_s[tid] = 0.f;
    if (tid < Tt) tm[tid] = 0.f;
    __syncthreads();
    const int* sp = esrc + g*Ee;
    const int* dp = edst + g*Ee;
    for (int e = tid; e < Ee; e += Nn)
        atomicAdd(&w_s[sp[e]], invs_s[dp[e]]);
    {
        unsigned m = g_mask[g*Nn + tid];
        float v = invs_s[tid];
        #pragma unroll
        for (int t = 0; t < Tt; t++) {
            float p = ((m >> t) & 1u) ? v : 0.f;
            #pragma unroll
            for (int d = 16; d > 0; d >>= 1)
                p += __shfl_xor_sync(0xffffffffu, p, d);
            if (lane == 0) atomicAdd(&tm[t], p);
        }
    }
    __syncthreads();
    g_w[g*Nn + tid] = invs_s[tid]*(w_s[tid] + invs_s[tid]);
    if (tid < Tt) g_tm[g*Tt + tid] = tm[tid];
}

// ------- agg1: smem-cached gather, LDS.128 quarter-warp edges ---------------
// 2 blocks per graph (512 nodes each), 1024 threads, 128KB feature cache.
// Lane split: q = lane>>3 (edge slot, 4 edges per LDS), l8 = lane&7
// (feature slot, 16B = 8 bf16 per lane).
__global__ void __launch_bounds__(1024, 1) agg1_kernel(const float* __restrict__ b1)
{
    extern __shared__ char sm[];
    uint4* Af   = (uint4*)sm;                       // [1024*8] = 128KB
    float* st   = (float*)(sm + 131072);            // Tt*Hh floats
    float* bias = (float*)(sm + 131072 + 2560);     // Hh floats
    int tid = threadIdx.x;
    int g = blockIdx.x >> 1, hs = blockIdx.x & 1;

    // stage features (coalesced uint4)
    {
        const uint4* src = (const uint4*)g_A + (size_t)g*(Nn*8);
        #pragma unroll
        for (int r = 0; r < 8; r++) Af[tid + r*1024] = __ldg(&src[tid + r*1024]);
    }
    if (tid < Tt*Hh) st[tid] = g_st1[tid];
    else if (tid < Tt*Hh + Hh) bias[tid - Tt*Hh] = b1[tid - Tt*Hh];
    __syncthreads();

    int lane = tid & 31, w = tid >> 5;
    int q = lane >> 3, l8 = lane & 7;
    float psum[8];
    #pragma unroll
    for (int j = 0; j < 8; j++) psum[j] = 0.f;

    #pragma unroll 1
    for (int k = 0; k < 16; k++) {
        int ln = hs*512 + w*16 + k;                  // local node id
        int bn = g*Nn + ln;
        int cnt = g_indeg[bn];
        int off = g_off[bn];
        float acc[8];
        #pragma unroll
        for (int j = 0; j < 8; j++) acc[j] = 0.f;
        int e = 0;
        for (; e + 8 <= cnt; e += 8) {
            int i0 = __ldg(&g_csr[off + e     + q]);
            int i1 = __ldg(&g_csr[off + e + 4 + q]);
            uint4 v0 = Af[i0*8 + l8];
            uint4 v1 = Af[i1*8 + l8];
            acc_bf16x8(acc, v0);
            acc_bf16x8(acc, v1);
        }
        for (; e < cnt; e += 4) {
            if (e + q < cnt) {
                int i0 = __ldg(&g_csr[off + e + q]);
                uint4 v0 = Af[i0*8 + l8];
                acc_bf16x8(acc, v0);
            }
        }
        // combine the four quarter-warp partials
        #pragma unroll
        for (int j = 0; j < 8; j++) {
            acc[j] += __shfl_xor_sync(0xffffffffu, acc[j], 8);
            acc[j] += __shfl_xor_sync(0xffffffffu, acc[j], 16);
        }
        if (q == 0) {
            unsigned mk = g_mask[bn];
            while (mk) {
                int t = __ffs(mk) - 1; mk &= mk - 1;
                #pragma unroll
                for (int j = 0; j < 8; j++) acc[j] += st[t*Hh + l8*8 + j];
            }
            uint4 sv = Af[ln*8 + l8];
            acc_bf16x8(acc, sv);
            float is = g_invs[bn];
            float fw = g_w[bn];
            #pragma unroll
            for (int j = 0; j < 8; j++) {
                float o = acc[j]*is + bias[l8*8 + j];
                o = (o >= 0.f) ? o : 0.01f*o;
                psum[j] += o*fw;
            }
        }
    }
    if (q == 0) {
        #pragma unroll
        for (int j = 0; j < 8; j++)
            atomicAdd(&g_P[g*Hh + l8*8 + j], psum[j]);
    }
}

// ------- head: add token-cross, W2 matvec, b2/toksum, pool, softmax ---------
__global__ void head_kernel(const float* __restrict__ W2, const float* __restrict__ b2,
                            const float* __restrict__ Wa, const float* __restrict__ ba,
                            float* __restrict__ out)
{
    __shared__ float P[Hh];
    __shared__ float emb[Hh];
    __shared__ float tm[Tt];
    int g = blockIdx.x, h = threadIdx.x;
    if (h < Tt) tm[h] = g_tm[g*Tt + h];
    __syncthreads();
    float p = g_P[g*Hh + h];
    #pragma unroll
    for (int t = 0; t < Tt; t++) p += g_st2p[t*Hh + h]*tm[t];
    P[h] = p;
    __syncthreads();
    const float scale = 1.f/(float)(Tt + Nn);
    float a = 0.f;
    for (int k = 0; k < Hh; k++) a += P[k]*W2[k*Hh + h];
    emb[h] = (a + (float)Nn*b2[h] + g_toksum[h]) * scale;
    __syncthreads();
    if (h == 0) {
        float l0 = ba[0], l1 = ba[1];
        for (int o = 0; o < Hh; o++) {
            l0 += emb[o]*Wa[o*2+0];
            l1 += emb[o]*Wa[o*2+1];
        }
        float mx = fmaxf(l0, l1);
        float e0 = expf(l0 - mx), e1 = expf(l1 - mx);
        float s = e0 + e1;
        out[g*2+0] = e0/s;
        out[g*2+1] = e1/s;
    }
}

// ---------------- launch ----------------------------------------------------
extern "C" void kernel_launch(void* const* d_in, const int* in_sizes, int n_in,
                              void* d_out, int out_size)
{
    const float* x    = (const float*)d_in[0];
    const float* tok  = (const float*)d_in[1];
    const float* W1   = (const float*)d_in[2];
    const float* b1   = (const float*)d_in[3];
    const float* W2   = (const float*)d_in[4];
    const float* b2   = (const float*)d_in[5];
    const float* Wa   = (const float*)d_in[6];
    const float* ba   = (const float*)d_in[7];
    const int*   esrc = (const int*)d_in[8];
    const int*   edst = (const int*)d_in[9];
    float* out = (float*)d_out;

    cudaFuncSetAttribute(agg1_kernel,
                         cudaFuncAttributeMaxDynamicSharedMemorySize, AGG_SMEM);

    csr_token_kernel<<<Bq + 1, Nn>>>(esrc, edst, tok, W1, b1, W2, b2);
    xpass_kernel<<<BN/64, 256>>>(x, W1, tok);
    wtok_kernel<<<Bq, Nn>>>(esrc, edst);
    agg1_kernel<<<Bq*2, 1024, AGG_SMEM>>>(b1);
    head_kernel<<<Bq, Hh>>>(W2, b2, Wa, ba, out);
}

// round 17
// speedup vs baseline: 1.1482x; 1.1482x over previous
#include <cuda_runtime.h>
#include <cuda_bf16.h>
#include <math.h>

#define Bq 64
#define Nn 1024
#define Ee 16384
#define Ff 128
#define Hh 64
#define Tt 10
#define BN (Bq*Nn)   // 65536

// agg1 dynamic smem: 128KB features + st(2560) + bias(256)
#define AGG_SMEM (131072 + 2560 + 256)

// ---------------- scratch (static device globals; no allocs allowed) --------
__device__ __nv_bfloat16 g_A[BN*Hh]; // layer1: bf16 invs[n]*(x@W1)[n]
__device__ int      g_csr[Bq*Ee];    // CSR-by-dst: LOCAL src ids (0..1023)
__device__ int      g_off[BN];       // absolute start offset into g_csr
__device__ int      g_indeg[BN];
__device__ unsigned g_mask[BN];      // 10-bit token->node mask
__device__ float    g_invs[BN];      // 1/sqrt(deg_node)
__device__ float    g_w[BN];         // invs[n]*(w[n]+invs[n]) pooling weight
__device__ float    g_tm[Bq*Tt];     // tmask[g][t] = sum_n mask[n,t]*invs[n]
__device__ float    g_st1[Tt*Hh];    // invsT[t] * (tokens@W1)[t,:]
__device__ float    g_st2p[Tt*Hh];   // invsT[t] * h1a_tok[t,:]  (pre-W2 cross)
__device__ float    g_toksum[Hh];    // sum_t out_tok2[t,:]
__device__ float    g_P[Bq*Hh];      // pooled pre-W2 node vectors (atomic accum)

// ---- helpers ----------------------------------------------------------------
__device__ __forceinline__ __nv_bfloat162 u2bf(unsigned u) {
    return *reinterpret_cast<__nv_bfloat162*>(&u);
}
__device__ __forceinline__ void acc_bf16x4(float4& a, uint2 v) {
    a.x += __uint_as_float(v.x << 16);
    a.y += __uint_as_float(v.x & 0xffff0000u);
    a.z += __uint_as_float(v.y << 16);
    a.w += __uint_as_float(v.y & 0xffff0000u);
}
__device__ __forceinline__ unsigned pack_bf16x2(float a, float b) {
    __nv_bfloat162 p = __float22bfloat162_rn(make_float2(a, b));
    return *reinterpret_cast<unsigned*>(&p);
}

// ---------------- CSR build (blocks 0-63) + token stream (block 64) ---------
__global__ void csr_token_kernel(const int* __restrict__ esrc, const int* __restrict__ edst,
                                 const float* __restrict__ tok,
                                 const float* __restrict__ W1, const float* __restrict__ b1,
                                 const float* __restrict__ W2, const float* __restrict__ b2)
{
    __shared__ union {
        struct { int cnt[Nn]; int wsum[32]; } c;
        struct {
            float tk[Tt][129];
            float nrm[Tt][Tt];
            float invsT[Tt], invdT[Tt];
            float h1l[Tt][Hh], h1a[Tt][Hh], h2l[Tt][Hh], ot2[Tt][Hh];
        } t;
    } u;
    int tid = threadIdx.x;

    if (blockIdx.x < Bq) {
        int b = blockIdx.x;
        int lane = tid & 31, wid = tid >> 5;
        u.c.cnt[tid] = 0;
        __syncthreads();
        const int* dp = edst + b*Ee;
        const int* sp = esrc + b*Ee;
        for (int e = tid; e < Ee; e += Nn) atomicAdd(&u.c.cnt[dp[e]], 1);
        __syncthreads();
        int c = u.c.cnt[tid];
        g_indeg[b*Nn + tid] = c;
        int v = c;
        for (int d = 1; d < 32; d <<= 1) {
            int uu = __shfl_up_sync(0xffffffffu, v, d);
            if (lane >= d) v += uu;
        }
        if (lane == 31) u.c.wsum[wid] = v;
        __syncthreads();
        if (tid < 32) {
            int s = u.c.wsum[tid];
            for (int d = 1; d < 32; d <<= 1) {
                int uu = __shfl_up_sync(0xffffffffu, s, d);
                if (tid >= d) s += uu;
            }
            u.c.wsum[tid] = s;
        }
        __syncthreads();
        int base = wid ? u.c.wsum[wid-1] : 0;
        int pos0 = b*Ee + base + (v - c);
        g_off[b*Nn + tid] = pos0;
        __syncthreads();
        u.c.cnt[tid] = pos0;
        __syncthreads();
        for (int e = tid; e < Ee; e += Nn) {
            int d = dp[e];
            int p = atomicAdd(&u.c.cnt[d], 1);
            g_csr[p] = sp[e];                 // LOCAL src id
        }
    } else {
        const int NT = 1024;
        for (int i = tid; i < Tt*Ff; i += NT) u.t.tk[i/Ff][i%Ff] = tok[i];
        __syncthreads();
        if (tid < Tt*Tt) {
            int i = tid/Tt, j = tid%Tt;
            float d = 0.f;
            for (int f = 0; f < Ff; f++) d += u.t.tk[i][f]*u.t.tk[j][f];
            float s = 1.f/(1.f+expf(-d));
            u.t.nrm[i][j] = (s >= 0.3f) ? 1.f : 0.f;
        }
        __syncthreads();
        if (tid < Tt) {
            float deg = 1.f;
            for (int i = 0; i < Tt; i++) deg += u.t.nrm[i][tid];
            u.t.invsT[tid] = rsqrtf(deg);
            u.t.invdT[tid] = 1.f/deg;
        }
        __syncthreads();
        if (tid < Tt*Tt) {
            int i = tid/Tt, j = tid%Tt;
            u.t.nrm[i][j] *= u.t.invsT[i]*u.t.invsT[j];
        }
        for (int idx = tid; idx < Tt*Hh; idx += NT) {
            int t = idx/Hh, h = idx%Hh;
            float a = 0.f;
            for (int f = 0; f < Ff; f++) a += u.t.tk[t][f]*W1[f*Hh+h];
            u.t.h1l[t][h] = a;
        }
        __syncthreads();
        for (int idx = tid; idx < Tt*Hh; idx += NT) {
            int t = idx/Hh, h = idx%Hh;
            float a = u.t.h1l[t][h]*u.t.invdT[t] + b1[h];
            for (int j = 0; j < Tt; j++) a += u.t.nrm[t][j]*u.t.h1l[j][h];
            float act = (a >= 0.f) ? a : 0.01f*a;
            u.t.h1a[t][h] = act;
            g_st1[idx]  = u.t.invsT[t]*u.t.h1l[t][h];
            g_st2p[idx] = u.t.invsT[t]*act;
        }
        __syncthreads();
        for (int idx = tid; idx < Tt*Hh; idx += NT) {
            int t = idx/Hh, h = idx%Hh;
            float a = 0.f;
            for (int k = 0; k < Hh; k++) a += u.t.h1a[t][k]*W2[k*Hh+h];
            u.t.h2l[t][h] = a;
        }
        __syncthreads();
        for (int idx = tid; idx < Tt*Hh; idx += NT) {
            int t = idx/Hh, h = idx%Hh;
            float a = u.t.h2l[t][h]*u.t.invdT[t] + b2[h];
            for (int j = 0; j < Tt; j++) a += u.t.nrm[t][j]*u.t.h2l[j][h];
            u.t.ot2[t][h] = a;
        }
        __syncthreads();
        if (tid < Hh) {
            float s = 0.f;
            for (int t = 0; t < Tt; t++) s += u.t.ot2[t][tid];
            g_toksum[tid] = s;
        }
        for (int i = tid; i < Bq*Hh; i += NT) g_P[i] = 0.f;
    }
}

// ------- fused x-pass: tf32 MMA for x@W1, fp32 token dots -> mask, deg ------
__global__ void xpass_kernel(const float* __restrict__ x, const float* __restrict__ W1,
                             const float* __restrict__ tok)
{
    __shared__ float xs2[64][68];
    __shared__ float ws[64][68];
    __shared__ float ts[Tt][64];
    __shared__ unsigned maskbuf[64];
    __shared__ float invsS[64];
    int tid = threadIdx.x;
    int bn0 = blockIdx.x * 64;
    int w = tid >> 5, t = tid & 31;
    int m0 = (w & 3) * 16;
    int h0 = (w >> 2) * 32;
    int ty = t >> 2, tk = t & 3;

    float acc[4][4];
    #pragma unroll
    for (int i = 0; i < 4; i++)
        #pragma unroll
        for (int j = 0; j < 4; j++) acc[i][j] = 0.f;
    float dacc[3] = {0.f, 0.f, 0.f};
    if (tid < 64) maskbuf[tid] = 0u;

    for (int c = 0; c < 2; c++) {
        __syncthreads();
        for (int idx = tid; idx < 4096; idx += 256) {
            int f = idx & 63, n = idx >> 6;
            xs2[n][f] = x[(bn0+n)*Ff + c*64 + f];
        }
        for (int idx = tid; idx < 4096; idx += 256) {
            int h = idx & 63, f = idx >> 6;
            ws[f][h] = W1[(c*64+f)*Hh + h];
        }
        for (int idx = tid; idx < Tt*64; idx += 256) {
            int f = idx & 63, tt = idx >> 6;
            ts[tt][f] = tok[tt*Ff + c*64 + f];
        }
        __syncthreads();
        #pragma unroll
        for (int r = 0; r < 3; r++) {
            int idx = tid + r*256;
            if (idx < 640) {
                int n = idx & 63, tt = idx >> 6;
                float a = dacc[r];
                #pragma unroll 8
                for (int f = 0; f < 64; f++) a += xs2[n][f]*ts[tt][f];
                dacc[r] = a;
            }
        }
        #pragma unroll
        for (int k8 = 0; k8 < 8; k8++) {
            int k0 = k8*8;
            unsigned a0 = __float_as_uint(xs2[m0+ty  ][k0+tk  ]);
            unsigned a1 = __float_as_uint(xs2[m0+ty+8][k0+tk  ]);
            unsigned a2 = __float_as_uint(xs2[m0+ty  ][k0+tk+4]);
            unsigned a3 = __float_as_uint(xs2[m0+ty+8][k0+tk+4]);
            #pragma unroll
            for (int ns = 0; ns < 4; ns++) {
                unsigned b0 = __float_as_uint(ws[k0+tk  ][h0+ns*8+ty]);
                unsigned b1 = __float_as_uint(ws[k0+tk+4][h0+ns*8+ty]);
                asm volatile(
                    "mma.sync.aligned.m16n8k8.row.col.f32.tf32.tf32.f32 "
                    "{%0,%1,%2,%3},{%4,%5,%6,%7},{%8,%9},{%0,%1,%2,%3};"
                    : "+f"(acc[ns][0]), "+f"(acc[ns][1]),
                      "+f"(acc[ns][2]), "+f"(acc[ns][3])
                    : "r"(a0), "r"(a1), "r"(a2), "r"(a3), "r"(b0), "r"(b1));
            }
        }
    }
    #pragma unroll
    for (int r = 0; r < 3; r++) {
        int idx = tid + r*256;
        if (idx < 640) {
            int n = idx & 63, tt = idx >> 6;
            float s = 1.f/(1.f+expf(-dacc[r]));
            if (s >= 0.1f) atomicOr(&maskbuf[n], 1u << tt);
        }
    }
    __syncthreads();
    if (tid < 64) {
        int bn = bn0 + tid;
        unsigned m = maskbuf[tid];
        float deg = 1.0f + (float)g_indeg[bn] + (float)__popc(m);
        float is = rsqrtf(deg);
        g_mask[bn] = m;
        g_invs[bn] = is;
        invsS[tid] = is;
    }
    __syncthreads();
    {
        unsigned* A32 = (unsigned*)g_A;
        int r0 = m0 + ty, r1 = r0 + 8;
        float s0 = invsS[r0], s1 = invsS[r1];
        int cb = (h0 >> 1) + tk;
        #pragma unroll
        for (int ns = 0; ns < 4; ns++) {
            A32[(bn0+r0)*32 + cb + ns*4] = pack_bf16x2(acc[ns][0]*s0, acc[ns][1]*s0);
            A32[(bn0+r1)*32 + cb + ns*4] = pack_bf16x2(acc[ns][2]*s1, acc[ns][3]*s1);
        }
    }
}

// ------- per-graph source weights + token-mask sums -------------------------
__global__ void wtok_kernel(const int* __restrict__ esrc, const int* __restrict__ edst)
{
    __shared__ float invs_s[Nn];
    __shared__ float w_s[Nn];
    __shared__ float tm[Tt];
    int g = blockIdx.x, tid = threadIdx.x;
    int lane = tid & 31;
    invs_s[tid] = g_invs[g*Nn + tid];
    w_s[tid] = 0.f;
    if (tid < Tt) tm[tid] = 0.f;
    __syncthreads();
    const int* sp = esrc + g*Ee;
    const int* dp = edst + g*Ee;
    for (int e = tid; e < Ee; e += Nn)
        atomicAdd(&w_s[sp[e]], invs_s[dp[e]]);
    {
        unsigned m = g_mask[g*Nn + tid];
        float v = invs_s[tid];
        #pragma unroll
        for (int t = 0; t < Tt; t++) {
            float p = ((m >> t) & 1u) ? v : 0.f;
            #pragma unroll
            for (int d = 16; d > 0; d >>= 1)
                p += __shfl_xor_sync(0xffffffffu, p, d);
            if (lane == 0) atomicAdd(&tm[t], p);
        }
    }
    __syncthreads();
    g_w[g*Nn + tid] = invs_s[tid]*(w_s[tid] + invs_s[tid]);
    if (tid < Tt) g_tm[g*Tt + tid] = tm[tid];
}

// ------- agg1: smem-cached gather (R15 layout) + 4-edge HADD2 trees ---------
// 2 blocks per graph, 1024 threads, 128KB feature cache; occupancy is
// smem-limited so the extra bf16 registers are free (R16 evidence).
__global__ void __launch_bounds__(1024, 1) agg1_kernel(const float* __restrict__ b1)
{
    extern __shared__ char sm[];
    uint2*  Af   = (uint2*)sm;                        // [1024*16] = 128KB
    float4* st   = (float4*)(sm + 131072);            // Tt*16
    float4* bias = (float4*)(sm + 131072 + 2560);     // 16
    int tid = threadIdx.x;
    int g = blockIdx.x >> 1, hs = blockIdx.x & 1;

    // stage features (coalesced uint4)
    {
        const uint4* src = (const uint4*)g_A + (size_t)g*(Nn*8);
        uint4* dv = (uint4*)Af;
        #pragma unroll
        for (int r = 0; r < 8; r++) dv[tid + r*1024] = __ldg(&src[tid + r*1024]);
    }
    {
        const float4* s1p = (const float4*)g_st1;
        if (tid < Tt*16) st[tid] = s1p[tid];
        else if (tid < Tt*16 + 16) bias[tid - Tt*16] = ((const float4*)b1)[tid - Tt*16];
    }
    __syncthreads();

    int lane = tid & 31, w = tid >> 5;
    int l16 = lane & 15, half = lane >> 4;
    float4 psum = make_float4(0.f, 0.f, 0.f, 0.f);

    #pragma unroll 1
    for (int k = 0; k < 16; k++) {
        int ln = hs*512 + w*16 + k;                   // local node id
        int bn = g*Nn + ln;
        int cnt = g_indeg[bn];
        int off = g_off[bn];
        float4 acc = make_float4(0.f, 0.f, 0.f, 0.f);
        int e = 0;
        for (; e + 8 <= cnt; e += 8) {
            int i0 = __ldg(&g_csr[off + e     + half]);
            int i1 = __ldg(&g_csr[off + e + 2 + half]);
            int i2 = __ldg(&g_csr[off + e + 4 + half]);
            int i3 = __ldg(&g_csr[off + e + 6 + half]);
            uint2 v0 = Af[i0*16 + l16];
            uint2 v1 = Af[i1*16 + l16];
            uint2 v2 = Af[i2*16 + l16];
            uint2 v3 = Af[i3*16 + l16];
            // 4-edge bf16 pairwise tree, single fp32 flush (R5-validated)
            __nv_bfloat162 sx = __hadd2(__hadd2(u2bf(v0.x), u2bf(v1.x)),
                                        __hadd2(u2bf(v2.x), u2bf(v3.x)));
            __nv_bfloat162 sy = __hadd2(__hadd2(u2bf(v0.y), u2bf(v1.y)),
                                        __hadd2(u2bf(v2.y), u2bf(v3.y)));
            unsigned ux = *reinterpret_cast<unsigned*>(&sx);
            unsigned uy = *reinterpret_cast<unsigned*>(&sy);
            acc.x += __uint_as_float(ux << 16);
            acc.y += __uint_as_float(ux & 0xffff0000u);
            acc.z += __uint_as_float(uy << 16);
            acc.w += __uint_as_float(uy & 0xffff0000u);
        }
        for (; e + 2 <= cnt; e += 2) {
            int i0 = __ldg(&g_csr[off + e + half]);
            uint2 v0 = Af[i0*16 + l16];
            acc_bf16x4(acc, v0);
        }
        if (e < cnt && half == 0) {
            int i0 = __ldg(&g_csr[off + e]);
            uint2 v0 = Af[i0*16 + l16];
            acc_bf16x4(acc, v0);
        }
        acc.x += __shfl_xor_sync(0xffffffffu, acc.x, 16);
        acc.y += __shfl_xor_sync(0xffffffffu, acc.y, 16);
        acc.z += __shfl_xor_sync(0xffffffffu, acc.z, 16);
        acc.w += __shfl_xor_sync(0xffffffffu, acc.w, 16);
        if (half == 0) {
            unsigned mk = g_mask[bn];
            while (mk) {
                int t = __ffs(mk) - 1; mk &= mk - 1;
                float4 v = st[t*16 + l16];
                acc.x += v.x; acc.y += v.y; acc.z += v.z; acc.w += v.w;
            }
            uint2 sv = Af[ln*16 + l16];
            acc_bf16x4(acc, sv);
            float is = g_invs[bn];
            float4 bb = bias[l16];
            float4 o;
            o.x = acc.x*is + bb.x; o.y = acc.y*is + bb.y;
            o.z = acc.z*is + bb.z; o.w = acc.w*is + bb.w;
            o.x = (o.x >= 0.f) ? o.x : 0.01f*o.x;
            o.y = (o.y >= 0.f) ? o.y : 0.01f*o.y;
            o.z = (o.z >= 0.f) ? o.z : 0.01f*o.z;
            o.w = (o.w >= 0.f) ? o.w : 0.01f*o.w;
            float fw = g_w[bn];
            psum.x += o.x*fw; psum.y += o.y*fw;
            psum.z += o.z*fw; psum.w += o.w*fw;
        }
    }
    if (half == 0) {
        atomicAdd(&g_P[g*Hh + l16*4+0], psum.x);
        atomicAdd(&g_P[g*Hh + l16*4+1], psum.y);
        atomicAdd(&g_P[g*Hh + l16*4+2], psum.z);
        atomicAdd(&g_P[g*Hh + l16*4+3], psum.w);
    }
}

// ------- head: add token-cross, W2 matvec, b2/toksum, pool, softmax ---------
__global__ void head_kernel(const float* __restrict__ W2, const float* __restrict__ b2,
                            const float* __restrict__ Wa, const float* __restrict__ ba,
                            float* __restrict__ out)
{
    __shared__ float P[Hh];
    __shared__ float emb[Hh];
    __shared__ float tm[Tt];
    int g = blockIdx.x, h = threadIdx.x;
    if (h < Tt) tm[h] = g_tm[g*Tt + h];
    __syncthreads();
    float p = g_P[g*Hh + h];
    #pragma unroll
    for (int t = 0; t < Tt; t++) p += g_st2p[t*Hh + h]*tm[t];
    P[h] = p;
    __syncthreads();
    const float scale = 1.f/(float)(Tt + Nn);
    float a = 0.f;
    for (int k = 0; k < Hh; k++) a += P[k]*W2[k*Hh + h];
    emb[h] = (a + (float)Nn*b2[h] + g_toksum[h]) * scale;
    __syncthreads();
    if (h == 0) {
        float l0 = ba[0], l1 = ba[1];
        for (int o = 0; o < Hh; o++) {
            l0 += emb[o]*Wa[o*2+0];
            l1 += emb[o]*Wa[o*2+1];
        }
        float mx = fmaxf(l0, l1);
        float e0 = expf(l0 - mx), e1 = expf(l1 - mx);
        float s = e0 + e1;
        out[g*2+0] = e0/s;
        out[g*2+1] = e1/s;
    }
}

// ---------------- launch ----------------------------------------------------
extern "C" void kernel_launch(void* const* d_in, const int* in_sizes, int n_in,
                              void* d_out, int out_size)
{
    const float* x    = (const float*)d_in[0];
    const float* tok  = (const float*)d_in[1];
    const float* W1   = (const float*)d_in[2];
    const float* b1   = (const float*)d_in[3];
    const float* W2   = (const float*)d_in[4];
    const float* b2   = (const float*)d_in[5];
    const float* Wa   = (const float*)d_in[6];
    const float* ba   = (const float*)d_in[7];
    const int*   esrc = (const int*)d_in[8];
    const int*   edst = (const int*)d_in[9];
    float* out = (float*)d_out;

    cudaFuncSetAttribute(agg1_kernel,
                         cudaFuncAttributeMaxDynamicSharedMemorySize, AGG_SMEM);

    csr_token_kernel<<<Bq + 1, Nn>>>(esrc, edst, tok, W1, b1, W2, b2);
    xpass_kernel<<<BN/64, 256>>>(x, W1, tok);
    wtok_kernel<<<Bq, Nn>>>(esrc, edst);
    agg1_kernel<<<Bq*2, 1024, AGG_SMEM>>>(b1);
    head_kernel<<<Bq, Hh>>>(W2, b2, Wa, ba, out);
}